// round 14
// baseline (speedup 1.0000x reference)
#include <cuda_runtime.h>
#include <cuda_bf16.h>

#define NE 3
#define BB 256
#define TT 168
#define DE 32
#define UU 256
#define U3 768
#define HH 24
#define BT (BB*TT)

typedef unsigned long long ull;

__device__ __forceinline__ ull pack2(float lo, float hi){ ull r; asm("mov.b64 %0,{%1,%2};":"=l"(r):"f"(lo),"f"(hi)); return r; }
__device__ __forceinline__ void unpack2(ull v, float&lo, float&hi){ asm("mov.b64 {%0,%1},%2;":"=f"(lo),"=f"(hi):"l"(v)); }
__device__ __forceinline__ void fma2(ull&d, ull a, ull b){ asm("fma.rn.f32x2 %0,%1,%2,%0;":"+l"(d):"l"(a),"l"(b)); }

__device__ __forceinline__ float sigm(float x){ return __fdividef(1.f, 1.f + __expf(-x)); }
__device__ __forceinline__ float tanh_(float x){
    float e = __expf(-2.f*fabsf(x));
    float t = __fdividef(1.f-e, 1.f+e);
    return copysignf(t,x);
}
__device__ __forceinline__ float tanha(float x){ float y; asm("tanh.approx.f32 %0,%1;":"=f"(y):"f"(x)); return y; }
__device__ __forceinline__ float blo(unsigned pk){ return __uint_as_float(pk << 16); }
__device__ __forceinline__ float bhi(unsigned pk){ return __uint_as_float(pk & 0xffff0000u); }

// ---------------- device scratch ----------------
__device__ __align__(16) __nv_bfloat16 g_eoh[NE][BT][UU]; // enc_out bf16
__device__ __align__(16) __nv_bfloat16 g_pjh[NE][BT][UU]; // enc_proj bf16
__device__ __align__(16) float g_h[2][NE][BB][UU];        // encoder hidden ping-pong
__device__ __align__(16) float g_hd[BB][UU];
__device__ __align__(16) float g_c[BB][U3];
__device__ __align__(16) float g_q[NE][BB][UU];
__device__ __align__(16) float g_dp[4][BB][U3];
__device__ __align__(16) float g_s1[BB][UU];
__device__ unsigned g_es[12];

__global__ void k_init(){
    int i = blockIdx.x*256 + threadIdx.x;   // 768*256 = 196608
    ((float*)g_h)[i] = 0.f;                  // zeros buffer 0 exactly (NE*BB*UU)
    if (i < BB*UU) ((float*)g_hd)[i] = 0.f;
    if (i < BB*U3) ((float*)g_c)[i]  = 0.f;
    if (i < 12)    g_es[i] = 0u;
}

// ---------------- encoder: SMEM-resident weights, 8-CTA group sync ----------------
#define E_SWU 0
#define E_SWX 24576
#define E_SH  27648
#define E_SXI 44544
#define E_TOT 46656

__global__ __launch_bounds__(256,1) void k_enc(const float* __restrict__ X, const float* __restrict__ W,
                                               const float* __restrict__ Uw, const float* __restrict__ bv){
    extern __shared__ float sm[];
    float* swU = sm + E_SWU;
    float* swX = sm + E_SWX;
    float* sh  = sm + E_SH;
    float* sxi = sm + E_SXI;

    const int cid = blockIdx.x;
    const int n = cid >> 5, rem = cid & 31;
    const int r0 = (rem >> 3) * 64, u0 = (rem & 7) * 32;
    const int gid = n*4 + (rem >> 3);
    const int tx = threadIdx.x, ul = tx & 31, grp = tx >> 5;

    for (int idx = tx; idx < 24576; idx += 256){
        int k = idx / 96, c = idx % 96;
        int g = c >> 5, cc = c & 31;
        swU[idx] = Uw[(size_t)n*UU*U3 + (size_t)k*U3 + g*256 + u0 + cc];
    }
    for (int idx = tx; idx < 3072; idx += 256){
        int k = idx / 96, c = idx % 96;
        int g = c >> 5, cc = c & 31;
        swX[idx] = W[(size_t)n*DE*U3 + (size_t)k*U3 + g*256 + u0 + cc];
    }
    const float bz = bv[n*U3 + u0+ul];
    const float br = bv[n*U3 + 256 + u0+ul];
    const float bn = bv[n*U3 + 512 + u0+ul];
    __syncthreads();

    __nv_bfloat16* eob = &g_eoh[n][0][0];

    for (int t = 0; t < TT; ++t){
        const float* hs = &g_h[t&1][n][0][0];
        #pragma unroll 8
        for (int i = 0; i < 64; ++i) sh[tx*66 + i] = __ldcg(hs + (size_t)(r0+i)*UU + tx);
        {
            int idx = tx;
            #pragma unroll
            for (int i = 0; i < 8; ++i, idx += 256){
                int row = idx >> 5, col = idx & 31;
                sxi[col*66 + row] = X[(((size_t)n*BB + r0+row)*TT + t)*DE + col];
            }
        }
        __syncthreads();

        ull az[4], ar[4], ax[4], ah[4];
        #pragma unroll
        for (int j=0;j<4;++j){ az[j]=pack2(bz,bz); ar[j]=pack2(br,br); ax[j]=pack2(bn,bn); ah[j]=pack2(0.f,0.f); }

        #pragma unroll 4
        for (int k = 0; k < 256; ++k){
            const float* wrow = swU + k*96;
            float wza = wrow[ul], wra = wrow[32+ul], wna = wrow[64+ul];
            ull wz = pack2(wza,wza), wr = pack2(wra,wra), wn = pack2(wna,wna);
            const float* hrow = sh + k*66 + grp*8;
            #pragma unroll
            for (int j=0;j<4;++j){
                ull h2 = *(const ull*)&hrow[2*j];
                fma2(az[j],h2,wz); fma2(ar[j],h2,wr); fma2(ah[j],h2,wn);
            }
        }
        #pragma unroll 4
        for (int k = 0; k < 32; ++k){
            const float* wrow = swX + k*96;
            float wza = wrow[ul], wra = wrow[32+ul], wna = wrow[64+ul];
            ull wz = pack2(wza,wza), wr = pack2(wra,wra), wn = pack2(wna,wna);
            const float* xrow = sxi + k*66 + grp*8;
            #pragma unroll
            for (int j=0;j<4;++j){
                ull x2 = *(const ull*)&xrow[2*j];
                fma2(az[j],x2,wz); fma2(ar[j],x2,wr); fma2(ax[j],x2,wn);
            }
        }

        float* hd = &g_h[(t+1)&1][n][0][0];
        #pragma unroll
        for (int j=0;j<4;++j){
            int rl = grp*8 + 2*j;
            float z0,z1,rg0,rg1,x0,x1,hh0,hh1;
            unpack2(az[j],z0,z1); unpack2(ar[j],rg0,rg1); unpack2(ax[j],x0,x1); unpack2(ah[j],hh0,hh1);
            float hp0 = sh[(u0+ul)*66 + rl];
            float hp1 = sh[(u0+ul)*66 + rl + 1];
            z0=sigm(z0); z1=sigm(z1); rg0=sigm(rg0); rg1=sigm(rg1);
            float n0 = tanh_(x0 + rg0*hh0), n1 = tanh_(x1 + rg1*hh1);
            float o0 = (1.f-z0)*hp0 + z0*n0;
            float o1 = (1.f-z1)*hp1 + z1*n1;
            hd[(size_t)(r0+rl)*UU + u0+ul]   = o0;
            hd[(size_t)(r0+rl+1)*UU + u0+ul] = o1;
            eob[((size_t)(r0+rl)*TT + t)*UU + u0+ul]   = __float2bfloat16_rn(o0);
            eob[((size_t)(r0+rl+1)*TT + t)*UU + u0+ul] = __float2bfloat16_rn(o1);
        }

        __threadfence();
        __syncthreads();
        if (tx == 0){
            atomicAdd(&g_es[gid], 1u);
            unsigned tgt = 8u*(unsigned)(t+1);
            while (*((volatile unsigned*)&g_es[gid]) < tgt) { }
        }
        __syncthreads();
    }
}

// ---------------- enc_proj GEMM: 8x2 register tile (measured 480us) ----------------
__global__ __launch_bounds__(256) void k_proj(const float* __restrict__ W1){
    const int cid = blockIdx.x;                 // 8064
    const int n = cid / 2688, rem = cid % 2688;
    const int r0 = (rem >> 2) * 64, j0 = (rem & 3) * 64;
    const int tx = threadIdx.x;
    const int ty = tx >> 5;
    const int tix = tx & 31;

    __shared__ __align__(16) float sa[64][66];
    __shared__ __align__(16) float sb[64][66];

    const __nv_bfloat16* A = &g_eoh[n][0][0];
    const float* Bw = W1 + (size_t)n*UU*UU;

    ull acc[4][2];
    #pragma unroll
    for (int rp=0;rp<4;++rp){ acc[rp][0]=pack2(0.f,0.f); acc[rp][1]=pack2(0.f,0.f); }

    for (int kc=0;kc<4;++kc){
        {
            int idx = tx;
            #pragma unroll
            for (int i=0;i<16;++i, idx+=256){
                int row = idx>>6, k = idx&63;
                sa[k][row] = __bfloat162float(A[(size_t)(r0+row)*UU + kc*64 + k]);
            }
            idx = tx;
            #pragma unroll
            for (int i=0;i<16;++i, idx+=256){
                int k = idx>>6, col = idx&63;
                sb[k][col] = Bw[(size_t)(kc*64+k)*UU + j0 + col];
            }
        }
        __syncthreads();
        #pragma unroll 2
        for (int k=0;k<64;++k){
            const float* ar = &sa[k][ty*8];
            ull a0 = *(const ull*)(ar+0);
            ull a1 = *(const ull*)(ar+2);
            ull a2 = *(const ull*)(ar+4);
            ull a3 = *(const ull*)(ar+6);
            ull bp = *(const ull*)&sb[k][tix*2];
            float b0,b1; unpack2(bp,b0,b1);
            ull w0 = pack2(b0,b0), w1 = pack2(b1,b1);
            fma2(acc[0][0],a0,w0); fma2(acc[0][1],a0,w1);
            fma2(acc[1][0],a1,w0); fma2(acc[1][1],a1,w1);
            fma2(acc[2][0],a2,w0); fma2(acc[2][1],a2,w1);
            fma2(acc[3][0],a3,w0); fma2(acc[3][1],a3,w1);
        }
        __syncthreads();
    }
    __nv_bfloat16* C = &g_pjh[n][0][0];
    #pragma unroll
    for (int rp=0;rp<4;++rp){
        float r0c0, r1c0, r0c1, r1c1;
        unpack2(acc[rp][0], r0c0, r1c0);
        unpack2(acc[rp][1], r0c1, r1c1);
        int rowA = r0 + ty*8 + 2*rp;
        float2 f0; f0.x = r0c0; f0.y = r0c1;
        float2 f1; f1.x = r1c0; f1.y = r1c1;
        *(__nv_bfloat162*)&C[(size_t)rowA*UU + j0 + tix*2]     = __float22bfloat162_rn(f0);
        *(__nv_bfloat162*)&C[(size_t)(rowA+1)*UU + j0 + tix*2] = __float22bfloat162_rn(f1);
    }
}

// ================= decoder: 4 kernels per step =================

// ---- A: K-split GRU GEMM (grid 128), float4 weight staging (measured 25.4us) ----
#define A_SMEM ((24576+16896)*4)
__global__ __launch_bounds__(256,1) void k_dA(const float* __restrict__ dW, const float* __restrict__ dU){
    extern __shared__ float sm[];
    float* swD = sm;
    float* sh  = sm + 24576;

    const int cid = blockIdx.x;
    const int tx = threadIdx.x;
    const int ul = tx & 31, grp = tx >> 5;
    const int kt  = cid >> 5;
    const int rem = cid & 31;
    const int r0  = (rem >> 3) * 64, u0 = (rem & 7) * 32;

    const float* wb = (kt < 3) ? (dW + (size_t)kt*256*U3) : dU;
    for (int idx = tx; idx < 6144; idx += 256){
        int k = idx / 24, c4 = idx - k*24;
        int col = c4*4, g = col >> 5, cc = col & 31;
        *(float4*)&swD[k*96 + col] = *(const float4*)(wb + (size_t)k*U3 + g*256 + u0 + cc);
    }
    const float* src; int stride, koff;
    if (kt < 3){ src = &g_c[0][0]; stride = U3; koff = kt*256; }
    else       { src = &g_hd[0][0]; stride = UU; koff = 0; }
    #pragma unroll 8
    for (int i = 0; i < 64; ++i) sh[tx*66 + i] = src[(size_t)(r0+i)*stride + koff + tx];
    __syncthreads();

    ull az[4], ar[4], an[4];
    #pragma unroll
    for (int j=0;j<4;++j){ az[j]=pack2(0.f,0.f); ar[j]=pack2(0.f,0.f); an[j]=pack2(0.f,0.f); }
    #pragma unroll 2
    for (int k = 0; k < 256; ++k){
        const float* wrow = swD + k*96;
        float wza = wrow[ul], wra = wrow[32+ul], wna = wrow[64+ul];
        ull wz = pack2(wza,wza), wr = pack2(wra,wra), wn = pack2(wna,wna);
        const float* hrow = sh + k*66 + grp*8;
        #pragma unroll
        for (int j=0;j<4;++j){
            ull h2 = *(const ull*)&hrow[2*j];
            fma2(az[j],h2,wz); fma2(ar[j],h2,wr); fma2(an[j],h2,wn);
        }
    }
    float* dp = &g_dp[kt][0][0];
    #pragma unroll
    for (int j=0;j<4;++j){
        int rl = grp*8 + 2*j; float a0,a1;
        unpack2(az[j],a0,a1); dp[(r0+rl)*U3 + u0+ul] = a0;       dp[(r0+rl+1)*U3 + u0+ul] = a1;
        unpack2(ar[j],a0,a1); dp[(r0+rl)*U3 + 256 + u0+ul] = a0; dp[(r0+rl+1)*U3 + 256 + u0+ul] = a1;
        unpack2(an[j],a0,a1); dp[(r0+rl)*U3 + 512 + u0+ul] = a0; dp[(r0+rl+1)*U3 + 512 + u0+ul] = a1;
    }
}

// ---- B: reduce partials + pointwise GRU (grid 256) ----
__global__ __launch_bounds__(256) void k_dB(const float* __restrict__ dW, const float* __restrict__ db,
                                            const float* __restrict__ dinp, int s){
    int r = blockIdx.x, u = threadIdx.x;
    float d  = dinp[r*HH + s];
    float zp = db[u]     + d*dW[(size_t)768*U3 + u];
    float rp = db[256+u] + d*dW[(size_t)768*U3 + 256+u];
    float nx = db[512+u] + d*dW[(size_t)768*U3 + 512+u];
    float nh = g_dp[3][r][512+u];
    zp += g_dp[0][r][u] + g_dp[1][r][u] + g_dp[2][r][u] + g_dp[3][r][u];
    rp += g_dp[0][r][256+u] + g_dp[1][r][256+u] + g_dp[2][r][256+u] + g_dp[3][r][256+u];
    nx += g_dp[0][r][512+u] + g_dp[1][r][512+u] + g_dp[2][r][512+u];
    float z = sigm(zp), rg = sigm(rp);
    float nn = tanh_(nx + rg*nh);
    float hp = g_hd[r][u];
    g_hd[r][u] = (1.f-z)*hp + z*nn;
}

// ---- C: q = h @ att_W2 (grid 96), float4 weight staging ----
#define C_SMEM ((8192+16896)*4)
__global__ __launch_bounds__(256,1) void k_dC(const float* __restrict__ W2){
    extern __shared__ float sm[];
    float* sw2 = sm;
    float* sh  = sm + 8192;

    const int cid = blockIdx.x;
    const int tx = threadIdx.x;
    const int ul = tx & 31, grp = tx >> 5;
    const int n2 = cid >> 5;
    const int rm = cid & 31;
    const int rr0 = (rm >> 3) * 64, v0 = (rm & 7) * 32;

    for (int idx = tx; idx < 2048; idx += 256){
        int k = idx >> 3, c4 = idx & 7;
        *(float4*)&sw2[k*32 + c4*4] =
            *(const float4*)(W2 + (size_t)n2*UU*UU + (size_t)k*UU + v0 + c4*4);
    }
    #pragma unroll 8
    for (int i = 0; i < 64; ++i) sh[tx*66 + i] = g_hd[rr0+i][tx];
    __syncthreads();

    ull ac[4];
    #pragma unroll
    for (int j=0;j<4;++j) ac[j] = pack2(0.f,0.f);
    #pragma unroll 2
    for (int k = 0; k < 256; ++k){
        float w = sw2[k*32 + ul];
        ull w2 = pack2(w,w);
        const float* hrow = sh + k*66 + grp*8;
        #pragma unroll
        for (int j=0;j<4;++j) fma2(ac[j], *(const ull*)&hrow[2*j], w2);
    }
    #pragma unroll
    for (int j=0;j<4;++j){
        int rl = grp*8 + 2*j; float a0,a1; unpack2(ac[j],a0,a1);
        g_q[n2][rr0+rl][v0+ul]   = a0;
        g_q[n2][rr0+rl+1][v0+ul] = a1;
    }
}

// ---- D: attention (R12 config; ONLY change: score loop unroll 3 -> 7) ----
__global__ __launch_bounds__(256) void k_dD(const float* __restrict__ av){
    __shared__ __align__(16) float q_s[256], v_s[256];
    __shared__ float sc_s[176];
    __shared__ __align__(16) float sred[1024];

    const int tx = threadIdx.x, lane = tx & 31, wid = tx >> 5;
    const int n3 = blockIdx.x >> 8, b = blockIdx.x & 255;

    q_s[tx] = g_q[n3][b][tx];
    v_s[tx] = av[n3*UU + tx];
    __syncthreads();

    const __nv_bfloat16* pj = &g_pjh[n3][0][0] + (size_t)b*TT*UU;
    #pragma unroll 7
    for (int ii = 0; ii < 21; ++ii){
        int t = wid*21 + ii;
        const uint2* row = (const uint2*)(pj + (size_t)t*UU);
        float acc = 0.f;
        #pragma unroll
        for (int j2 = 0; j2 < 2; ++j2){
            int v = j2*128 + 4*lane;
            uint2 pk = row[j2*32 + lane];
            float4 qv = *(const float4*)&q_s[v];
            float4 vv = *(const float4*)&v_s[v];
            acc += tanha(blo(pk.x) + qv.x) * vv.x;
            acc += tanha(bhi(pk.x) + qv.y) * vv.y;
            acc += tanha(blo(pk.y) + qv.z) * vv.z;
            acc += tanha(bhi(pk.y) + qv.w) * vv.w;
        }
        #pragma unroll
        for (int o = 16; o > 0; o >>= 1) acc += __shfl_xor_sync(0xffffffffu, acc, o);
        if (lane == 0) sc_s[t] = acc;
    }
    __syncthreads();
    if (wid == 0){
        float m = -1e30f;
        for (int t = lane; t < TT; t += 32) m = fmaxf(m, sc_s[t]);
        #pragma unroll
        for (int o = 16; o > 0; o >>= 1) m = fmaxf(m, __shfl_xor_sync(0xffffffffu, m, o));
        float ss = 0.f;
        for (int t = lane; t < TT; t += 32){ float e2 = __expf(sc_s[t]-m); sc_s[t] = e2; ss += e2; }
        #pragma unroll
        for (int o = 16; o > 0; o >>= 1) ss += __shfl_xor_sync(0xffffffffu, ss, o);
        float inv = __fdividef(1.f, ss);
        for (int t = lane; t < TT; t += 32) sc_s[t] *= inv;
    }
    __syncthreads();
    {
        int tg = tx >> 6, uq = tx & 63;
        const __nv_bfloat16* eob = &g_eoh[n3][0][0] + (size_t)b*TT*UU;
        float4 a = make_float4(0.f,0.f,0.f,0.f);
        #pragma unroll 6
        for (int i = 0; i < 42; ++i){
            int t = tg + 4*i;
            uint2 e = __ldcs((const uint2*)(eob + (size_t)t*UU) + uq);
            float w = sc_s[t];
            a.x += w*blo(e.x); a.y += w*bhi(e.x);
            a.z += w*blo(e.y); a.w += w*bhi(e.y);
        }
        ((float4*)sred)[tg*64 + uq] = a;
    }
    __syncthreads();
    {
        int uq = tx >> 2, comp = tx & 3;
        float sum = sred[(0*64 + uq)*4 + comp] + sred[(1*64 + uq)*4 + comp]
                  + sred[(2*64 + uq)*4 + comp] + sred[(3*64 + uq)*4 + comp];
        g_c[b][n3*UU + tx] = sum;
    }
}

// ---------------- head part 1 ----------------
__global__ __launch_bounds__(256) void k_h1(const float* __restrict__ W1, const float* __restrict__ b1){
    const int rem = blockIdx.x;          // 32
    const int r0 = (rem>>2)*32, j0 = (rem&3)*64;
    const int tx = threadIdx.x, ul = tx&63, grp = tx>>6;
    __shared__ __align__(16) float sh[256][34];
    ull acc[4];
    #pragma unroll
    for (int j=0;j<4;++j) acc[j]=pack2(0.f,0.f);
    for (int cc=0;cc<4;++cc){
        const float* src = (cc==0) ? &g_hd[0][0] : (&g_c[0][0] + (cc-1)*256);
        int stride = (cc==0) ? UU : U3;
        __syncthreads();
        #pragma unroll 8
        for (int i=0;i<32;++i) sh[tx][i] = src[(r0+i)*stride + tx];
        __syncthreads();
        const float* wp = W1 + cc*256*UU + j0 + ul;
        #pragma unroll 2
        for (int k=0;k<256;++k){
            float w = wp[k*UU];
            ull w2 = pack2(w,w);
            #pragma unroll
            for (int j=0;j<4;++j) fma2(acc[j], *(const ull*)&sh[k][(grp*4+j)*2], w2);
        }
    }
    float bb = b1[j0+ul];
    #pragma unroll
    for (int j=0;j<4;++j){
        int rl=(grp*4+j)*2; float a0,a1; unpack2(acc[j],a0,a1);
        g_s1[r0+rl][j0+ul]   = a0+bb;
        g_s1[r0+rl+1][j0+ul] = a1+bb;
    }
}

// ---------------- head part 2 ----------------
__global__ __launch_bounds__(256) void k_h2(const float* __restrict__ ef, const float* __restrict__ eW,
        const float* __restrict__ eb, const float* __restrict__ W1, const float* __restrict__ w2v,
        const float* __restrict__ b2, float* __restrict__ out){
    const int b = blockIdx.x, tx = threadIdx.x, lane = tx&31, wid = tx>>5;
    __shared__ __align__(16) float se[256][26];
    __shared__ float sf[384];
    __shared__ float prt[8][24];
    sf[tx < 384 ? tx : 0] = ef[b*384 + (tx < 384 ? tx : 0)];
    if (tx < 128) sf[256+tx] = ef[b*384 + 256 + tx];
    __syncthreads();
    float wk[16];
    #pragma unroll
    for (int k=0;k<16;++k) wk[k] = eW[k*UU + tx];
    float ebv = eb[tx];
    #pragma unroll
    for (int h=0;h<24;++h){
        float a = ebv;
        #pragma unroll
        for (int k=0;k<16;++k) a += sf[h*16+k]*wk[k];
        se[tx][h] = fmaxf(a, 0.f);
    }
    __syncthreads();
    ull y2[12];
    #pragma unroll
    for (int p=0;p<12;++p) y2[p]=pack2(0.f,0.f);
    const float* wp = W1 + 1024*UU + tx;
    #pragma unroll 2
    for (int k=0;k<256;++k){
        float w = wp[k*UU];
        ull w2 = pack2(w,w);
        #pragma unroll
        for (int p=0;p<12;++p) fma2(y2[p], *(const ull*)&se[k][2*p], w2);
    }
    float sp = g_s1[b][tx];
    float wo = w2v[tx];
    float ct[24];
    #pragma unroll
    for (int p=0;p<12;++p){
        float a0,a1; unpack2(y2[p],a0,a1);
        ct[2*p]   = fmaxf(sp+a0, 0.f)*wo;
        ct[2*p+1] = fmaxf(sp+a1, 0.f)*wo;
    }
    #pragma unroll
    for (int h=0;h<24;++h){
        #pragma unroll
        for (int o=16;o>0;o>>=1) ct[h] += __shfl_xor_sync(0xffffffffu, ct[h], o);
    }
    if (lane==0){
        #pragma unroll
        for (int h=0;h<24;++h) prt[wid][h] = ct[h];
    }
    __syncthreads();
    if (tx < 24){
        float s2 = b2[0];
        #pragma unroll
        for (int w=0;w<8;++w) s2 += prt[w][tx];
        out[b*HH + tx] = s2;
    }
}

extern "C" void kernel_launch(void* const* d_in, const int* in_sizes, int n_in,
                              void* d_out, int out_size){
    const float* enc_in = (const float*)d_in[0];
    const float* dec_in = (const float*)d_in[1];
    const float* ext_f  = (const float*)d_in[2];
    const float* enc_W  = (const float*)d_in[3];
    const float* enc_U  = (const float*)d_in[4];
    const float* enc_b  = (const float*)d_in[5];
    const float* att_W1 = (const float*)d_in[6];
    const float* att_W2 = (const float*)d_in[7];
    const float* att_v  = (const float*)d_in[8];
    const float* dec_W  = (const float*)d_in[9];
    const float* dec_U  = (const float*)d_in[10];
    const float* dec_b  = (const float*)d_in[11];
    const float* ext_W  = (const float*)d_in[12];
    const float* ext_b  = (const float*)d_in[13];
    const float* out1_W = (const float*)d_in[14];
    const float* out1_b = (const float*)d_in[15];
    const float* out2_W = (const float*)d_in[16];
    const float* out2_b = (const float*)d_in[17];
    float* out = (float*)d_out;

    const int enc_smem = E_TOT * 4;   // 186624 B
    cudaFuncSetAttribute(k_enc, cudaFuncAttributeMaxDynamicSharedMemorySize, enc_smem);
    cudaFuncSetAttribute(k_dA, cudaFuncAttributeMaxDynamicSharedMemorySize, A_SMEM);
    cudaFuncSetAttribute(k_dC, cudaFuncAttributeMaxDynamicSharedMemorySize, C_SMEM);

    k_init<<<768,  256>>>();
    k_enc <<<96,   256, enc_smem>>>(enc_in, enc_W, enc_U, enc_b);
    k_proj<<<8064, 256>>>(att_W1);

    for (int s = 0; s < HH; ++s){
        k_dA<<<128, 256, A_SMEM>>>(dec_W, dec_U);
        k_dB<<<256, 256>>>(dec_W, dec_b, dec_in, s);
        k_dC<<<96,  256, C_SMEM>>>(att_W2);
        k_dD<<<768, 256>>>(att_v);
    }

    k_h1<<<32,  256>>>(out1_W, out1_b);
    k_h2<<<256, 256>>>(ext_f, ext_W, ext_b, out1_W, out2_W, out2_b, out);
}

// round 15
// speedup vs baseline: 1.0971x; 1.0971x over previous
#include <cuda_runtime.h>
#include <cuda_bf16.h>

#define NE 3
#define BB 256
#define TT 168
#define DE 32
#define UU 256
#define U3 768
#define HH 24
#define BT (BB*TT)
#define STR 68

typedef unsigned long long ull;

__device__ __forceinline__ ull pack2(float lo, float hi){ ull r; asm("mov.b64 %0,{%1,%2};":"=l"(r):"f"(lo),"f"(hi)); return r; }
__device__ __forceinline__ void unpack2(ull v, float&lo, float&hi){ asm("mov.b64 {%0,%1},%2;":"=f"(lo),"=f"(hi):"l"(v)); }
__device__ __forceinline__ void fma2(ull&d, ull a, ull b){ asm("fma.rn.f32x2 %0,%1,%2,%0;":"+l"(d):"l"(a),"l"(b)); }

__device__ __forceinline__ float sigm(float x){ return __fdividef(1.f, 1.f + __expf(-x)); }
__device__ __forceinline__ float tanh_(float x){
    float e = __expf(-2.f*fabsf(x));
    float t = __fdividef(1.f-e, 1.f+e);
    return copysignf(t,x);
}
__device__ __forceinline__ float tanha(float x){ float y; asm("tanh.approx.f32 %0,%1;":"=f"(y):"f"(x)); return y; }
__device__ __forceinline__ float blo(unsigned pk){ return __uint_as_float(pk << 16); }
__device__ __forceinline__ float bhi(unsigned pk){ return __uint_as_float(pk & 0xffff0000u); }

// ---------------- device scratch ----------------
__device__ __align__(16) __nv_bfloat16 g_eoh[NE][BT][UU]; // enc_out bf16
__device__ __align__(16) __nv_bfloat16 g_pjh[NE][BT][UU]; // enc_proj bf16
__device__ __align__(16) float g_h[2][NE][BB][UU];        // encoder hidden ping-pong
__device__ __align__(16) float g_hd[BB][UU];
__device__ __align__(16) float g_c[BB][U3];
__device__ __align__(16) float g_q[NE][BB][UU];
__device__ __align__(16) float g_dp[4][BB][U3];
__device__ __align__(16) float g_s1[BB][UU];
__device__ unsigned g_es[12];

__global__ void k_init(){
    int i = blockIdx.x*256 + threadIdx.x;   // 768*256 = 196608
    ((float*)g_h)[i] = 0.f;                  // zeros buffer 0 exactly (NE*BB*UU)
    if (i < BB*UU) ((float*)g_hd)[i] = 0.f;
    if (i < BB*U3) ((float*)g_c)[i]  = 0.f;
    if (i < 12)    g_es[i] = 0u;
}

// ---------------- encoder: SMEM-resident weights, 8-CTA group sync ----------------
#define E_SWU 0
#define E_SWX 24576
#define E_SH  27648
#define E_SXI (27648 + 256*STR)
#define E_TOT (27648 + 256*STR + 32*STR)

__global__ __launch_bounds__(256,1) void k_enc(const float* __restrict__ X, const float* __restrict__ W,
                                               const float* __restrict__ Uw, const float* __restrict__ bv){
    extern __shared__ float sm[];
    float* swU = sm + E_SWU;
    float* swX = sm + E_SWX;
    float* sh  = sm + E_SH;
    float* sxi = sm + E_SXI;

    const int cid = blockIdx.x;
    const int n = cid >> 5, rem = cid & 31;
    const int r0 = (rem >> 3) * 64, u0 = (rem & 7) * 32;
    const int gid = n*4 + (rem >> 3);
    const int tx = threadIdx.x, ul = tx & 31, grp = tx >> 5;

    for (int idx = tx; idx < 24576; idx += 256){
        int k = idx / 96, c = idx % 96;
        int g = c >> 5, cc = c & 31;
        swU[idx] = Uw[(size_t)n*UU*U3 + (size_t)k*U3 + g*256 + u0 + cc];
    }
    for (int idx = tx; idx < 3072; idx += 256){
        int k = idx / 96, c = idx % 96;
        int g = c >> 5, cc = c & 31;
        swX[idx] = W[(size_t)n*DE*U3 + (size_t)k*U3 + g*256 + u0 + cc];
    }
    const float bz = bv[n*U3 + u0+ul];
    const float br = bv[n*U3 + 256 + u0+ul];
    const float bn = bv[n*U3 + 512 + u0+ul];
    __syncthreads();

    __nv_bfloat16* eob = &g_eoh[n][0][0];

    for (int t = 0; t < TT; ++t){
        const float* hs = &g_h[t&1][n][0][0];
        #pragma unroll 8
        for (int i = 0; i < 64; ++i) sh[tx*STR + i] = __ldcg(hs + (size_t)(r0+i)*UU + tx);
        {
            int idx = tx;
            #pragma unroll
            for (int i = 0; i < 8; ++i, idx += 256){
                int row = idx >> 5, col = idx & 31;
                sxi[col*STR + row] = X[(((size_t)n*BB + r0+row)*TT + t)*DE + col];
            }
        }
        __syncthreads();

        ull az[4], ar[4], ax[4], ah[4];
        #pragma unroll
        for (int j=0;j<4;++j){ az[j]=pack2(bz,bz); ar[j]=pack2(br,br); ax[j]=pack2(bn,bn); ah[j]=pack2(0.f,0.f); }

        #pragma unroll 4
        for (int k = 0; k < 256; ++k){
            const float* wrow = swU + k*96;
            float wza = wrow[ul], wra = wrow[32+ul], wna = wrow[64+ul];
            ull wz = pack2(wza,wza), wr = pack2(wra,wra), wn = pack2(wna,wna);
            const float* hrow = sh + k*STR + grp*8;
            ulonglong2 hA = *(const ulonglong2*)(hrow);
            ulonglong2 hB = *(const ulonglong2*)(hrow + 4);
            fma2(az[0],hA.x,wz); fma2(ar[0],hA.x,wr); fma2(ah[0],hA.x,wn);
            fma2(az[1],hA.y,wz); fma2(ar[1],hA.y,wr); fma2(ah[1],hA.y,wn);
            fma2(az[2],hB.x,wz); fma2(ar[2],hB.x,wr); fma2(ah[2],hB.x,wn);
            fma2(az[3],hB.y,wz); fma2(ar[3],hB.y,wr); fma2(ah[3],hB.y,wn);
        }
        #pragma unroll 4
        for (int k = 0; k < 32; ++k){
            const float* wrow = swX + k*96;
            float wza = wrow[ul], wra = wrow[32+ul], wna = wrow[64+ul];
            ull wz = pack2(wza,wza), wr = pack2(wra,wra), wn = pack2(wna,wna);
            const float* xrow = sxi + k*STR + grp*8;
            ulonglong2 xA = *(const ulonglong2*)(xrow);
            ulonglong2 xB = *(const ulonglong2*)(xrow + 4);
            fma2(az[0],xA.x,wz); fma2(ar[0],xA.x,wr); fma2(ax[0],xA.x,wn);
            fma2(az[1],xA.y,wz); fma2(ar[1],xA.y,wr); fma2(ax[1],xA.y,wn);
            fma2(az[2],xB.x,wz); fma2(ar[2],xB.x,wr); fma2(ax[2],xB.x,wn);
            fma2(az[3],xB.y,wz); fma2(ar[3],xB.y,wr); fma2(ax[3],xB.y,wn);
        }

        float* hd = &g_h[(t+1)&1][n][0][0];
        #pragma unroll
        for (int j=0;j<4;++j){
            int rl = grp*8 + 2*j;
            float z0,z1,rg0,rg1,x0,x1,hh0,hh1;
            unpack2(az[j],z0,z1); unpack2(ar[j],rg0,rg1); unpack2(ax[j],x0,x1); unpack2(ah[j],hh0,hh1);
            float hp0 = sh[(u0+ul)*STR + rl];
            float hp1 = sh[(u0+ul)*STR + rl + 1];
            z0=sigm(z0); z1=sigm(z1); rg0=sigm(rg0); rg1=sigm(rg1);
            float n0 = tanh_(x0 + rg0*hh0), n1 = tanh_(x1 + rg1*hh1);
            float o0 = (1.f-z0)*hp0 + z0*n0;
            float o1 = (1.f-z1)*hp1 + z1*n1;
            hd[(size_t)(r0+rl)*UU + u0+ul]   = o0;
            hd[(size_t)(r0+rl+1)*UU + u0+ul] = o1;
            eob[((size_t)(r0+rl)*TT + t)*UU + u0+ul]   = __float2bfloat16_rn(o0);
            eob[((size_t)(r0+rl+1)*TT + t)*UU + u0+ul] = __float2bfloat16_rn(o1);
        }

        __threadfence();
        __syncthreads();
        if (tx == 0){
            atomicAdd(&g_es[gid], 1u);
            unsigned tgt = 8u*(unsigned)(t+1);
            while (*((volatile unsigned*)&g_es[gid]) < tgt) { }
        }
        __syncthreads();
    }
}

// ---------------- enc_proj GEMM: 8x2 register tile (measured 480us, unchanged) ----------------
__global__ __launch_bounds__(256) void k_proj(const float* __restrict__ W1){
    const int cid = blockIdx.x;                 // 8064
    const int n = cid / 2688, rem = cid % 2688;
    const int r0 = (rem >> 2) * 64, j0 = (rem & 3) * 64;
    const int tx = threadIdx.x;
    const int ty = tx >> 5;
    const int tix = tx & 31;

    __shared__ __align__(16) float sa[64][66];
    __shared__ __align__(16) float sb[64][66];

    const __nv_bfloat16* A = &g_eoh[n][0][0];
    const float* Bw = W1 + (size_t)n*UU*UU;

    ull acc[4][2];
    #pragma unroll
    for (int rp=0;rp<4;++rp){ acc[rp][0]=pack2(0.f,0.f); acc[rp][1]=pack2(0.f,0.f); }

    for (int kc=0;kc<4;++kc){
        {
            int idx = tx;
            #pragma unroll
            for (int i=0;i<16;++i, idx+=256){
                int row = idx>>6, k = idx&63;
                sa[k][row] = __bfloat162float(A[(size_t)(r0+row)*UU + kc*64 + k]);
            }
            idx = tx;
            #pragma unroll
            for (int i=0;i<16;++i, idx+=256){
                int k = idx>>6, col = idx&63;
                sb[k][col] = Bw[(size_t)(kc*64+k)*UU + j0 + col];
            }
        }
        __syncthreads();
        #pragma unroll 2
        for (int k=0;k<64;++k){
            const float* ar = &sa[k][ty*8];
            ull a0 = *(const ull*)(ar+0);
            ull a1 = *(const ull*)(ar+2);
            ull a2 = *(const ull*)(ar+4);
            ull a3 = *(const ull*)(ar+6);
            ull bp = *(const ull*)&sb[k][tix*2];
            float b0,b1; unpack2(bp,b0,b1);
            ull w0 = pack2(b0,b0), w1 = pack2(b1,b1);
            fma2(acc[0][0],a0,w0); fma2(acc[0][1],a0,w1);
            fma2(acc[1][0],a1,w0); fma2(acc[1][1],a1,w1);
            fma2(acc[2][0],a2,w0); fma2(acc[2][1],a2,w1);
            fma2(acc[3][0],a3,w0); fma2(acc[3][1],a3,w1);
        }
        __syncthreads();
    }
    __nv_bfloat16* C = &g_pjh[n][0][0];
    #pragma unroll
    for (int rp=0;rp<4;++rp){
        float r0c0, r1c0, r0c1, r1c1;
        unpack2(acc[rp][0], r0c0, r1c0);
        unpack2(acc[rp][1], r0c1, r1c1);
        int rowA = r0 + ty*8 + 2*rp;
        float2 f0; f0.x = r0c0; f0.y = r0c1;
        float2 f1; f1.x = r1c0; f1.y = r1c1;
        *(__nv_bfloat162*)&C[(size_t)rowA*UU + j0 + tix*2]     = __float22bfloat162_rn(f0);
        *(__nv_bfloat162*)&C[(size_t)(rowA+1)*UU + j0 + tix*2] = __float22bfloat162_rn(f1);
    }
}

// ================= decoder: 4 kernels per step =================

// ---- A: K-split GRU GEMM (grid 128), float4 staging + LDS.128 rows ----
#define A_SMEM ((24576 + 256*STR)*4)
__global__ __launch_bounds__(256,1) void k_dA(const float* __restrict__ dW, const float* __restrict__ dU){
    extern __shared__ float sm[];
    float* swD = sm;
    float* sh  = sm + 24576;

    const int cid = blockIdx.x;
    const int tx = threadIdx.x;
    const int ul = tx & 31, grp = tx >> 5;
    const int kt  = cid >> 5;
    const int rem = cid & 31;
    const int r0  = (rem >> 3) * 64, u0 = (rem & 7) * 32;

    const float* wb = (kt < 3) ? (dW + (size_t)kt*256*U3) : dU;
    for (int idx = tx; idx < 6144; idx += 256){
        int k = idx / 24, c4 = idx - k*24;
        int col = c4*4, g = col >> 5, cc = col & 31;
        *(float4*)&swD[k*96 + col] = *(const float4*)(wb + (size_t)k*U3 + g*256 + u0 + cc);
    }
    const float* src; int stride, koff;
    if (kt < 3){ src = &g_c[0][0]; stride = U3; koff = kt*256; }
    else       { src = &g_hd[0][0]; stride = UU; koff = 0; }
    #pragma unroll 8
    for (int i = 0; i < 64; ++i) sh[tx*STR + i] = src[(size_t)(r0+i)*stride + koff + tx];
    __syncthreads();

    ull az[4], ar[4], an[4];
    #pragma unroll
    for (int j=0;j<4;++j){ az[j]=pack2(0.f,0.f); ar[j]=pack2(0.f,0.f); an[j]=pack2(0.f,0.f); }
    #pragma unroll 2
    for (int k = 0; k < 256; ++k){
        const float* wrow = swD + k*96;
        float wza = wrow[ul], wra = wrow[32+ul], wna = wrow[64+ul];
        ull wz = pack2(wza,wza), wr = pack2(wra,wra), wn = pack2(wna,wna);
        const float* hrow = sh + k*STR + grp*8;
        ulonglong2 hA = *(const ulonglong2*)(hrow);
        ulonglong2 hB = *(const ulonglong2*)(hrow + 4);
        fma2(az[0],hA.x,wz); fma2(ar[0],hA.x,wr); fma2(an[0],hA.x,wn);
        fma2(az[1],hA.y,wz); fma2(ar[1],hA.y,wr); fma2(an[1],hA.y,wn);
        fma2(az[2],hB.x,wz); fma2(ar[2],hB.x,wr); fma2(an[2],hB.x,wn);
        fma2(az[3],hB.y,wz); fma2(ar[3],hB.y,wr); fma2(an[3],hB.y,wn);
    }
    float* dp = &g_dp[kt][0][0];
    #pragma unroll
    for (int j=0;j<4;++j){
        int rl = grp*8 + 2*j; float a0,a1;
        unpack2(az[j],a0,a1); dp[(r0+rl)*U3 + u0+ul] = a0;       dp[(r0+rl+1)*U3 + u0+ul] = a1;
        unpack2(ar[j],a0,a1); dp[(r0+rl)*U3 + 256 + u0+ul] = a0; dp[(r0+rl+1)*U3 + 256 + u0+ul] = a1;
        unpack2(an[j],a0,a1); dp[(r0+rl)*U3 + 512 + u0+ul] = a0; dp[(r0+rl+1)*U3 + 512 + u0+ul] = a1;
    }
}

// ---- B: reduce partials + pointwise GRU (grid 256) ----
__global__ __launch_bounds__(256) void k_dB(const float* __restrict__ dW, const float* __restrict__ db,
                                            const float* __restrict__ dinp, int s){
    int r = blockIdx.x, u = threadIdx.x;
    float d  = dinp[r*HH + s];
    float zp = db[u]     + d*dW[(size_t)768*U3 + u];
    float rp = db[256+u] + d*dW[(size_t)768*U3 + 256+u];
    float nx = db[512+u] + d*dW[(size_t)768*U3 + 512+u];
    float nh = g_dp[3][r][512+u];
    zp += g_dp[0][r][u] + g_dp[1][r][u] + g_dp[2][r][u] + g_dp[3][r][u];
    rp += g_dp[0][r][256+u] + g_dp[1][r][256+u] + g_dp[2][r][256+u] + g_dp[3][r][256+u];
    nx += g_dp[0][r][512+u] + g_dp[1][r][512+u] + g_dp[2][r][512+u];
    float z = sigm(zp), rg = sigm(rp);
    float nn = tanh_(nx + rg*nh);
    float hp = g_hd[r][u];
    g_hd[r][u] = (1.f-z)*hp + z*nn;
}

// ---- C: q = h @ att_W2 (grid 96), float4 staging + LDS.128 rows ----
#define C_SMEM ((8192 + 256*STR)*4)
__global__ __launch_bounds__(256,1) void k_dC(const float* __restrict__ W2){
    extern __shared__ float sm[];
    float* sw2 = sm;
    float* sh  = sm + 8192;

    const int cid = blockIdx.x;
    const int tx = threadIdx.x;
    const int ul = tx & 31, grp = tx >> 5;
    const int n2 = cid >> 5;
    const int rm = cid & 31;
    const int rr0 = (rm >> 3) * 64, v0 = (rm & 7) * 32;

    for (int idx = tx; idx < 2048; idx += 256){
        int k = idx >> 3, c4 = idx & 7;
        *(float4*)&sw2[k*32 + c4*4] =
            *(const float4*)(W2 + (size_t)n2*UU*UU + (size_t)k*UU + v0 + c4*4);
    }
    #pragma unroll 8
    for (int i = 0; i < 64; ++i) sh[tx*STR + i] = g_hd[rr0+i][tx];
    __syncthreads();

    ull ac[4];
    #pragma unroll
    for (int j=0;j<4;++j) ac[j] = pack2(0.f,0.f);
    #pragma unroll 2
    for (int k = 0; k < 256; ++k){
        float w = sw2[k*32 + ul];
        ull w2 = pack2(w,w);
        const float* hrow = sh + k*STR + grp*8;
        ulonglong2 hA = *(const ulonglong2*)(hrow);
        ulonglong2 hB = *(const ulonglong2*)(hrow + 4);
        fma2(ac[0],hA.x,w2); fma2(ac[1],hA.y,w2);
        fma2(ac[2],hB.x,w2); fma2(ac[3],hB.y,w2);
    }
    #pragma unroll
    for (int j=0;j<4;++j){
        int rl = grp*8 + 2*j; float a0,a1; unpack2(ac[j],a0,a1);
        g_q[n2][rr0+rl][v0+ul]   = a0;
        g_q[n2][rr0+rl+1][v0+ul] = a1;
    }
}

// ---- D: attention (exact R12 config — best measured) ----
__global__ __launch_bounds__(256) void k_dD(const float* __restrict__ av){
    __shared__ __align__(16) float q_s[256], v_s[256];
    __shared__ float sc_s[176];
    __shared__ __align__(16) float sred[1024];

    const int tx = threadIdx.x, lane = tx & 31, wid = tx >> 5;
    const int n3 = blockIdx.x >> 8, b = blockIdx.x & 255;

    q_s[tx] = g_q[n3][b][tx];
    v_s[tx] = av[n3*UU + tx];
    __syncthreads();

    const __nv_bfloat16* pj = &g_pjh[n3][0][0] + (size_t)b*TT*UU;
    #pragma unroll 3
    for (int ii = 0; ii < 21; ++ii){
        int t = wid*21 + ii;
        const uint2* row = (const uint2*)(pj + (size_t)t*UU);
        float acc = 0.f;
        #pragma unroll
        for (int j2 = 0; j2 < 2; ++j2){
            int v = j2*128 + 4*lane;
            uint2 pk = row[j2*32 + lane];
            float4 qv = *(const float4*)&q_s[v];
            float4 vv = *(const float4*)&v_s[v];
            acc += tanha(blo(pk.x) + qv.x) * vv.x;
            acc += tanha(bhi(pk.x) + qv.y) * vv.y;
            acc += tanha(blo(pk.y) + qv.z) * vv.z;
            acc += tanha(bhi(pk.y) + qv.w) * vv.w;
        }
        #pragma unroll
        for (int o = 16; o > 0; o >>= 1) acc += __shfl_xor_sync(0xffffffffu, acc, o);
        if (lane == 0) sc_s[t] = acc;
    }
    __syncthreads();
    if (wid == 0){
        float m = -1e30f;
        for (int t = lane; t < TT; t += 32) m = fmaxf(m, sc_s[t]);
        #pragma unroll
        for (int o = 16; o > 0; o >>= 1) m = fmaxf(m, __shfl_xor_sync(0xffffffffu, m, o));
        float ss = 0.f;
        for (int t = lane; t < TT; t += 32){ float e2 = __expf(sc_s[t]-m); sc_s[t] = e2; ss += e2; }
        #pragma unroll
        for (int o = 16; o > 0; o >>= 1) ss += __shfl_xor_sync(0xffffffffu, ss, o);
        float inv = __fdividef(1.f, ss);
        for (int t = lane; t < TT; t += 32) sc_s[t] *= inv;
    }
    __syncthreads();
    {
        int tg = tx >> 6, uq = tx & 63;
        const __nv_bfloat16* eob = &g_eoh[n3][0][0] + (size_t)b*TT*UU;
        float4 a = make_float4(0.f,0.f,0.f,0.f);
        #pragma unroll 6
        for (int i = 0; i < 42; ++i){
            int t = tg + 4*i;
            uint2 e = __ldcs((const uint2*)(eob + (size_t)t*UU) + uq);
            float w = sc_s[t];
            a.x += w*blo(e.x); a.y += w*bhi(e.x);
            a.z += w*blo(e.y); a.w += w*bhi(e.y);
        }
        ((float4*)sred)[tg*64 + uq] = a;
    }
    __syncthreads();
    {
        int uq = tx >> 2, comp = tx & 3;
        float sum = sred[(0*64 + uq)*4 + comp] + sred[(1*64 + uq)*4 + comp]
                  + sred[(2*64 + uq)*4 + comp] + sred[(3*64 + uq)*4 + comp];
        g_c[b][n3*UU + tx] = sum;
    }
}

// ---------------- head part 1 ----------------
__global__ __launch_bounds__(256) void k_h1(const float* __restrict__ W1, const float* __restrict__ b1){
    const int rem = blockIdx.x;          // 32
    const int r0 = (rem>>2)*32, j0 = (rem&3)*64;
    const int tx = threadIdx.x, ul = tx&63, grp = tx>>6;
    __shared__ __align__(16) float sh[256][34];
    ull acc[4];
    #pragma unroll
    for (int j=0;j<4;++j) acc[j]=pack2(0.f,0.f);
    for (int cc=0;cc<4;++cc){
        const float* src = (cc==0) ? &g_hd[0][0] : (&g_c[0][0] + (cc-1)*256);
        int stride = (cc==0) ? UU : U3;
        __syncthreads();
        #pragma unroll 8
        for (int i=0;i<32;++i) sh[tx][i] = src[(r0+i)*stride + tx];
        __syncthreads();
        const float* wp = W1 + cc*256*UU + j0 + ul;
        #pragma unroll 2
        for (int k=0;k<256;++k){
            float w = wp[k*UU];
            ull w2 = pack2(w,w);
            #pragma unroll
            for (int j=0;j<4;++j) fma2(acc[j], *(const ull*)&sh[k][(grp*4+j)*2], w2);
        }
    }
    float bb = b1[j0+ul];
    #pragma unroll
    for (int j=0;j<4;++j){
        int rl=(grp*4+j)*2; float a0,a1; unpack2(acc[j],a0,a1);
        g_s1[r0+rl][j0+ul]   = a0+bb;
        g_s1[r0+rl+1][j0+ul] = a1+bb;
    }
}

// ---------------- head part 2 ----------------
__global__ __launch_bounds__(256) void k_h2(const float* __restrict__ ef, const float* __restrict__ eW,
        const float* __restrict__ eb, const float* __restrict__ W1, const float* __restrict__ w2v,
        const float* __restrict__ b2, float* __restrict__ out){
    const int b = blockIdx.x, tx = threadIdx.x, lane = tx&31, wid = tx>>5;
    __shared__ __align__(16) float se[256][26];
    __shared__ float sf[384];
    __shared__ float prt[8][24];
    sf[tx < 384 ? tx : 0] = ef[b*384 + (tx < 384 ? tx : 0)];
    if (tx < 128) sf[256+tx] = ef[b*384 + 256 + tx];
    __syncthreads();
    float wk[16];
    #pragma unroll
    for (int k=0;k<16;++k) wk[k] = eW[k*UU + tx];
    float ebv = eb[tx];
    #pragma unroll
    for (int h=0;h<24;++h){
        float a = ebv;
        #pragma unroll
        for (int k=0;k<16;++k) a += sf[h*16+k]*wk[k];
        se[tx][h] = fmaxf(a, 0.f);
    }
    __syncthreads();
    ull y2[12];
    #pragma unroll
    for (int p=0;p<12;++p) y2[p]=pack2(0.f,0.f);
    const float* wp = W1 + 1024*UU + tx;
    #pragma unroll 2
    for (int k=0;k<256;++k){
        float w = wp[k*UU];
        ull w2 = pack2(w,w);
        #pragma unroll
        for (int p=0;p<12;++p) fma2(y2[p], *(const ull*)&se[k][2*p], w2);
    }
    float sp = g_s1[b][tx];
    float wo = w2v[tx];
    float ct[24];
    #pragma unroll
    for (int p=0;p<12;++p){
        float a0,a1; unpack2(y2[p],a0,a1);
        ct[2*p]   = fmaxf(sp+a0, 0.f)*wo;
        ct[2*p+1] = fmaxf(sp+a1, 0.f)*wo;
    }
    #pragma unroll
    for (int h=0;h<24;++h){
        #pragma unroll
        for (int o=16;o>0;o>>=1) ct[h] += __shfl_xor_sync(0xffffffffu, ct[h], o);
    }
    if (lane==0){
        #pragma unroll
        for (int h=0;h<24;++h) prt[wid][h] = ct[h];
    }
    __syncthreads();
    if (tx < 24){
        float s2 = b2[0];
        #pragma unroll
        for (int w=0;w<8;++w) s2 += prt[w][tx];
        out[b*HH + tx] = s2;
    }
}

extern "C" void kernel_launch(void* const* d_in, const int* in_sizes, int n_in,
                              void* d_out, int out_size){
    const float* enc_in = (const float*)d_in[0];
    const float* dec_in = (const float*)d_in[1];
    const float* ext_f  = (const float*)d_in[2];
    const float* enc_W  = (const float*)d_in[3];
    const float* enc_U  = (const float*)d_in[4];
    const float* enc_b  = (const float*)d_in[5];
    const float* att_W1 = (const float*)d_in[6];
    const float* att_W2 = (const float*)d_in[7];
    const float* att_v  = (const float*)d_in[8];
    const float* dec_W  = (const float*)d_in[9];
    const float* dec_U  = (const float*)d_in[10];
    const float* dec_b  = (const float*)d_in[11];
    const float* ext_W  = (const float*)d_in[12];
    const float* ext_b  = (const float*)d_in[13];
    const float* out1_W = (const float*)d_in[14];
    const float* out1_b = (const float*)d_in[15];
    const float* out2_W = (const float*)d_in[16];
    const float* out2_b = (const float*)d_in[17];
    float* out = (float*)d_out;

    const int enc_smem = E_TOT * 4;
    cudaFuncSetAttribute(k_enc, cudaFuncAttributeMaxDynamicSharedMemorySize, enc_smem);
    cudaFuncSetAttribute(k_dA, cudaFuncAttributeMaxDynamicSharedMemorySize, A_SMEM);
    cudaFuncSetAttribute(k_dC, cudaFuncAttributeMaxDynamicSharedMemorySize, C_SMEM);

    k_init<<<768,  256>>>();
    k_enc <<<96,   256, enc_smem>>>(enc_in, enc_W, enc_U, enc_b);
    k_proj<<<8064, 256>>>(att_W1);

    for (int s = 0; s < HH; ++s){
        k_dA<<<128, 256, A_SMEM>>>(dec_W, dec_U);
        k_dB<<<256, 256>>>(dec_W, dec_b, dec_in, s);
        k_dC<<<96,  256, C_SMEM>>>(att_W2);
        k_dD<<<768, 256>>>(att_v);
    }

    k_h1<<<32,  256>>>(out1_W, out1_b);
    k_h2<<<256, 256>>>(ext_f, ext_W, ext_b, out1_W, out2_W, out2_b, out);
}

// round 16
// speedup vs baseline: 1.1148x; 1.0161x over previous
#include <cuda_runtime.h>
#include <cuda_bf16.h>

#define NE 3
#define BB 256
#define TT 168
#define DE 32
#define UU 256
#define U3 768
#define HH 24
#define BT (BB*TT)
#define STR 68

typedef unsigned long long ull;

__device__ __forceinline__ ull pack2(float lo, float hi){ ull r; asm("mov.b64 %0,{%1,%2};":"=l"(r):"f"(lo),"f"(hi)); return r; }
__device__ __forceinline__ void unpack2(ull v, float&lo, float&hi){ asm("mov.b64 {%0,%1},%2;":"=f"(lo),"=f"(hi):"l"(v)); }
__device__ __forceinline__ void fma2(ull&d, ull a, ull b){ asm("fma.rn.f32x2 %0,%1,%2,%0;":"+l"(d):"l"(a),"l"(b)); }

__device__ __forceinline__ float sigm(float x){ return __fdividef(1.f, 1.f + __expf(-x)); }
__device__ __forceinline__ float tanh_(float x){
    float e = __expf(-2.f*fabsf(x));
    float t = __fdividef(1.f-e, 1.f+e);
    return copysignf(t,x);
}
__device__ __forceinline__ float tanha(float x){ float y; asm("tanh.approx.f32 %0,%1;":"=f"(y):"f"(x)); return y; }
__device__ __forceinline__ float blo(unsigned pk){ return __uint_as_float(pk << 16); }
__device__ __forceinline__ float bhi(unsigned pk){ return __uint_as_float(pk & 0xffff0000u); }

// ---------------- device scratch ----------------
__device__ __align__(16) __nv_bfloat16 g_eoh[NE][BT][UU];
__device__ __align__(16) __nv_bfloat16 g_pjh[NE][BT][UU];
__device__ __align__(16) float g_h[2][NE][BB][UU];
__device__ __align__(16) float g_hd[BB][UU];
__device__ __align__(16) float g_c[BB][U3];
__device__ __align__(16) float g_q[NE][BB][UU];
__device__ __align__(16) float g_dp[4][BB][U3];
__device__ __align__(16) float g_s1[BB][UU];
__device__ unsigned g_es[12];

__global__ void k_init(){
    int i = blockIdx.x*256 + threadIdx.x;
    ((float*)g_h)[i] = 0.f;
    if (i < BB*UU) ((float*)g_hd)[i] = 0.f;
    if (i < BB*U3) ((float*)g_c)[i]  = 0.f;
    if (i < 12)    g_es[i] = 0u;
}

// ---------------- encoder: k-paired layout, no weight duplication ----------------
// swU2[k2*192 + c*2 + (k&1)], sh2[k2*132 + r*2 + (k&1)]
#define E_SWU 0
#define E_SWX 24576
#define E_SH  27648
#define E_SXI 44544
#define E_TOT 46656

__global__ __launch_bounds__(256,1) void k_enc(const float* __restrict__ X, const float* __restrict__ W,
                                               const float* __restrict__ Uw, const float* __restrict__ bv){
    extern __shared__ float sm[];
    float* swU = sm + E_SWU;
    float* swX = sm + E_SWX;
    float* sh  = sm + E_SH;
    float* sxi = sm + E_SXI;

    const int cid = blockIdx.x;
    const int n = cid >> 5, rem = cid & 31;
    const int r0 = (rem >> 3) * 64, u0 = (rem & 7) * 32;
    const int gid = n*4 + (rem >> 3);
    const int tx = threadIdx.x, ul = tx & 31, grp = tx >> 5;

    for (int idx = tx; idx < 24576; idx += 256){
        int k = idx / 96, c = idx % 96;
        int g = c >> 5, cc = c & 31;
        swU[(k>>1)*192 + c*2 + (k&1)] = Uw[(size_t)n*UU*U3 + (size_t)k*U3 + g*256 + u0 + cc];
    }
    for (int idx = tx; idx < 3072; idx += 256){
        int k = idx / 96, c = idx % 96;
        int g = c >> 5, cc = c & 31;
        swX[(k>>1)*192 + c*2 + (k&1)] = W[(size_t)n*DE*U3 + (size_t)k*U3 + g*256 + u0 + cc];
    }
    const float bz = bv[n*U3 + u0+ul];
    const float br = bv[n*U3 + 256 + u0+ul];
    const float bn = bv[n*U3 + 512 + u0+ul];
    __syncthreads();

    __nv_bfloat16* eob = &g_eoh[n][0][0];

    for (int t = 0; t < TT; ++t){
        const float* hs = &g_h[t&1][n][0][0];
        {
            float* shc = sh + (tx>>1)*132 + (tx&1);
            #pragma unroll 8
            for (int i = 0; i < 64; ++i) shc[i*2] = __ldcg(hs + (size_t)(r0+i)*UU + tx);
        }
        {
            int idx = tx;
            #pragma unroll
            for (int i = 0; i < 8; ++i, idx += 256){
                int row = idx >> 5, col = idx & 31;
                sxi[(col>>1)*132 + row*2 + (col&1)] = X[(((size_t)n*BB + r0+row)*TT + t)*DE + col];
            }
        }
        __syncthreads();

        ull az[8], ar[8], ax[8], ah[8];
        #pragma unroll
        for (int j=0;j<8;++j){ az[j]=pack2(bz,0.f); ar[j]=pack2(br,0.f); ax[j]=pack2(bn,0.f); ah[j]=pack2(0.f,0.f); }

        #pragma unroll 4
        for (int k2 = 0; k2 < 128; ++k2){
            const float* wrow = swU + k2*192 + 2*ul;
            ull wz = *(const ull*)(wrow);
            ull wr = *(const ull*)(wrow + 64);
            ull wn = *(const ull*)(wrow + 128);
            const float* hrow = sh + k2*132 + grp*16;
            ulonglong2 hA = *(const ulonglong2*)(hrow);
            ulonglong2 hB = *(const ulonglong2*)(hrow + 4);
            ulonglong2 hC = *(const ulonglong2*)(hrow + 8);
            ulonglong2 hD = *(const ulonglong2*)(hrow + 12);
            fma2(az[0],hA.x,wz); fma2(ar[0],hA.x,wr); fma2(ah[0],hA.x,wn);
            fma2(az[1],hA.y,wz); fma2(ar[1],hA.y,wr); fma2(ah[1],hA.y,wn);
            fma2(az[2],hB.x,wz); fma2(ar[2],hB.x,wr); fma2(ah[2],hB.x,wn);
            fma2(az[3],hB.y,wz); fma2(ar[3],hB.y,wr); fma2(ah[3],hB.y,wn);
            fma2(az[4],hC.x,wz); fma2(ar[4],hC.x,wr); fma2(ah[4],hC.x,wn);
            fma2(az[5],hC.y,wz); fma2(ar[5],hC.y,wr); fma2(ah[5],hC.y,wn);
            fma2(az[6],hD.x,wz); fma2(ar[6],hD.x,wr); fma2(ah[6],hD.x,wn);
            fma2(az[7],hD.y,wz); fma2(ar[7],hD.y,wr); fma2(ah[7],hD.y,wn);
        }
        #pragma unroll 4
        for (int k2 = 0; k2 < 16; ++k2){
            const float* wrow = swX + k2*192 + 2*ul;
            ull wz = *(const ull*)(wrow);
            ull wr = *(const ull*)(wrow + 64);
            ull wn = *(const ull*)(wrow + 128);
            const float* xrow = sxi + k2*132 + grp*16;
            ulonglong2 xA = *(const ulonglong2*)(xrow);
            ulonglong2 xB = *(const ulonglong2*)(xrow + 4);
            ulonglong2 xC = *(const ulonglong2*)(xrow + 8);
            ulonglong2 xD = *(const ulonglong2*)(xrow + 12);
            fma2(az[0],xA.x,wz); fma2(ar[0],xA.x,wr); fma2(ax[0],xA.x,wn);
            fma2(az[1],xA.y,wz); fma2(ar[1],xA.y,wr); fma2(ax[1],xA.y,wn);
            fma2(az[2],xB.x,wz); fma2(ar[2],xB.x,wr); fma2(ax[2],xB.x,wn);
            fma2(az[3],xB.y,wz); fma2(ar[3],xB.y,wr); fma2(ax[3],xB.y,wn);
            fma2(az[4],xC.x,wz); fma2(ar[4],xC.x,wr); fma2(ax[4],xC.x,wn);
            fma2(az[5],xC.y,wz); fma2(ar[5],xC.y,wr); fma2(ax[5],xC.y,wn);
            fma2(az[6],xD.x,wz); fma2(ar[6],xD.x,wr); fma2(ax[6],xD.x,wn);
            fma2(az[7],xD.y,wz); fma2(ar[7],xD.y,wr); fma2(ax[7],xD.y,wn);
        }

        float* hd = &g_h[(t+1)&1][n][0][0];
        const int uc = u0 + ul;
        #pragma unroll
        for (int j=0;j<8;++j){
            int rl = grp*8 + j;
            float e0,e1;
            unpack2(az[j],e0,e1); float zv = e0+e1;
            unpack2(ar[j],e0,e1); float rv = e0+e1;
            unpack2(ax[j],e0,e1); float xv = e0+e1;
            unpack2(ah[j],e0,e1); float hv = e0+e1;
            float hp = sh[(uc>>1)*132 + rl*2 + (uc&1)];
            float z = sigm(zv), rg = sigm(rv);
            float nn = tanh_(xv + rg*hv);
            float o = (1.f-z)*hp + z*nn;
            hd[(size_t)(r0+rl)*UU + uc] = o;
            eob[((size_t)(r0+rl)*TT + t)*UU + uc] = __float2bfloat16_rn(o);
        }

        __threadfence();
        __syncthreads();
        if (tx == 0){
            atomicAdd(&g_es[gid], 1u);
            unsigned tgt = 8u*(unsigned)(t+1);
            while (*((volatile unsigned*)&g_es[gid]) < tgt) { }
        }
        __syncthreads();
    }
}

// ---------------- enc_proj GEMM (R15, unchanged) ----------------
__global__ __launch_bounds__(256) void k_proj(const float* __restrict__ W1){
    const int cid = blockIdx.x;
    const int n = cid / 2688, rem = cid % 2688;
    const int r0 = (rem >> 2) * 64, j0 = (rem & 3) * 64;
    const int tx = threadIdx.x;
    const int ty = tx >> 5;
    const int tix = tx & 31;

    __shared__ __align__(16) float sa[64][66];
    __shared__ __align__(16) float sb[64][66];

    const __nv_bfloat16* A = &g_eoh[n][0][0];
    const float* Bw = W1 + (size_t)n*UU*UU;

    ull acc[4][2];
    #pragma unroll
    for (int rp=0;rp<4;++rp){ acc[rp][0]=pack2(0.f,0.f); acc[rp][1]=pack2(0.f,0.f); }

    for (int kc=0;kc<4;++kc){
        {
            int idx = tx;
            #pragma unroll
            for (int i=0;i<16;++i, idx+=256){
                int row = idx>>6, k = idx&63;
                sa[k][row] = __bfloat162float(A[(size_t)(r0+row)*UU + kc*64 + k]);
            }
            idx = tx;
            #pragma unroll
            for (int i=0;i<16;++i, idx+=256){
                int k = idx>>6, col = idx&63;
                sb[k][col] = Bw[(size_t)(kc*64+k)*UU + j0 + col];
            }
        }
        __syncthreads();
        #pragma unroll 2
        for (int k=0;k<64;++k){
            const float* ar = &sa[k][ty*8];
            ull a0 = *(const ull*)(ar+0);
            ull a1 = *(const ull*)(ar+2);
            ull a2 = *(const ull*)(ar+4);
            ull a3 = *(const ull*)(ar+6);
            ull bp = *(const ull*)&sb[k][tix*2];
            float b0,b1; unpack2(bp,b0,b1);
            ull w0 = pack2(b0,b0), w1 = pack2(b1,b1);
            fma2(acc[0][0],a0,w0); fma2(acc[0][1],a0,w1);
            fma2(acc[1][0],a1,w0); fma2(acc[1][1],a1,w1);
            fma2(acc[2][0],a2,w0); fma2(acc[2][1],a2,w1);
            fma2(acc[3][0],a3,w0); fma2(acc[3][1],a3,w1);
        }
        __syncthreads();
    }
    __nv_bfloat16* C = &g_pjh[n][0][0];
    #pragma unroll
    for (int rp=0;rp<4;++rp){
        float r0c0, r1c0, r0c1, r1c1;
        unpack2(acc[rp][0], r0c0, r1c0);
        unpack2(acc[rp][1], r0c1, r1c1);
        int rowA = r0 + ty*8 + 2*rp;
        float2 f0; f0.x = r0c0; f0.y = r0c1;
        float2 f1; f1.x = r1c0; f1.y = r1c1;
        *(__nv_bfloat162*)&C[(size_t)rowA*UU + j0 + tix*2]     = __float22bfloat162_rn(f0);
        *(__nv_bfloat162*)&C[(size_t)(rowA+1)*UU + j0 + tix*2] = __float22bfloat162_rn(f1);
    }
}

// ================= decoder: 4 kernels per step (R15, unchanged) =================

#define A_SMEM ((24576 + 256*STR)*4)
__global__ __launch_bounds__(256,1) void k_dA(const float* __restrict__ dW, const float* __restrict__ dU){
    extern __shared__ float sm[];
    float* swD = sm;
    float* sh  = sm + 24576;

    const int cid = blockIdx.x;
    const int tx = threadIdx.x;
    const int ul = tx & 31, grp = tx >> 5;
    const int kt  = cid >> 5;
    const int rem = cid & 31;
    const int r0  = (rem >> 3) * 64, u0 = (rem & 7) * 32;

    const float* wb = (kt < 3) ? (dW + (size_t)kt*256*U3) : dU;
    for (int idx = tx; idx < 6144; idx += 256){
        int k = idx / 24, c4 = idx - k*24;
        int col = c4*4, g = col >> 5, cc = col & 31;
        *(float4*)&swD[k*96 + col] = *(const float4*)(wb + (size_t)k*U3 + g*256 + u0 + cc);
    }
    const float* src; int stride, koff;
    if (kt < 3){ src = &g_c[0][0]; stride = U3; koff = kt*256; }
    else       { src = &g_hd[0][0]; stride = UU; koff = 0; }
    #pragma unroll 8
    for (int i = 0; i < 64; ++i) sh[tx*STR + i] = src[(size_t)(r0+i)*stride + koff + tx];
    __syncthreads();

    ull az[4], ar[4], an[4];
    #pragma unroll
    for (int j=0;j<4;++j){ az[j]=pack2(0.f,0.f); ar[j]=pack2(0.f,0.f); an[j]=pack2(0.f,0.f); }
    #pragma unroll 2
    for (int k = 0; k < 256; ++k){
        const float* wrow = swD + k*96;
        float wza = wrow[ul], wra = wrow[32+ul], wna = wrow[64+ul];
        ull wz = pack2(wza,wza), wr = pack2(wra,wra), wn = pack2(wna,wna);
        const float* hrow = sh + k*STR + grp*8;
        ulonglong2 hA = *(const ulonglong2*)(hrow);
        ulonglong2 hB = *(const ulonglong2*)(hrow + 4);
        fma2(az[0],hA.x,wz); fma2(ar[0],hA.x,wr); fma2(an[0],hA.x,wn);
        fma2(az[1],hA.y,wz); fma2(ar[1],hA.y,wr); fma2(an[1],hA.y,wn);
        fma2(az[2],hB.x,wz); fma2(ar[2],hB.x,wr); fma2(an[2],hB.x,wn);
        fma2(az[3],hB.y,wz); fma2(ar[3],hB.y,wr); fma2(an[3],hB.y,wn);
    }
    float* dp = &g_dp[kt][0][0];
    #pragma unroll
    for (int j=0;j<4;++j){
        int rl = grp*8 + 2*j; float a0,a1;
        unpack2(az[j],a0,a1); dp[(r0+rl)*U3 + u0+ul] = a0;       dp[(r0+rl+1)*U3 + u0+ul] = a1;
        unpack2(ar[j],a0,a1); dp[(r0+rl)*U3 + 256 + u0+ul] = a0; dp[(r0+rl+1)*U3 + 256 + u0+ul] = a1;
        unpack2(an[j],a0,a1); dp[(r0+rl)*U3 + 512 + u0+ul] = a0; dp[(r0+rl+1)*U3 + 512 + u0+ul] = a1;
    }
}

__global__ __launch_bounds__(256) void k_dB(const float* __restrict__ dW, const float* __restrict__ db,
                                            const float* __restrict__ dinp, int s){
    int r = blockIdx.x, u = threadIdx.x;
    float d  = dinp[r*HH + s];
    float zp = db[u]     + d*dW[(size_t)768*U3 + u];
    float rp = db[256+u] + d*dW[(size_t)768*U3 + 256+u];
    float nx = db[512+u] + d*dW[(size_t)768*U3 + 512+u];
    float nh = g_dp[3][r][512+u];
    zp += g_dp[0][r][u] + g_dp[1][r][u] + g_dp[2][r][u] + g_dp[3][r][u];
    rp += g_dp[0][r][256+u] + g_dp[1][r][256+u] + g_dp[2][r][256+u] + g_dp[3][r][256+u];
    nx += g_dp[0][r][512+u] + g_dp[1][r][512+u] + g_dp[2][r][512+u];
    float z = sigm(zp), rg = sigm(rp);
    float nn = tanh_(nx + rg*nh);
    float hp = g_hd[r][u];
    g_hd[r][u] = (1.f-z)*hp + z*nn;
}

#define C_SMEM ((8192 + 256*STR)*4)
__global__ __launch_bounds__(256,1) void k_dC(const float* __restrict__ W2){
    extern __shared__ float sm[];
    float* sw2 = sm;
    float* sh  = sm + 8192;

    const int cid = blockIdx.x;
    const int tx = threadIdx.x;
    const int ul = tx & 31, grp = tx >> 5;
    const int n2 = cid >> 5;
    const int rm = cid & 31;
    const int rr0 = (rm >> 3) * 64, v0 = (rm & 7) * 32;

    for (int idx = tx; idx < 2048; idx += 256){
        int k = idx >> 3, c4 = idx & 7;
        *(float4*)&sw2[k*32 + c4*4] =
            *(const float4*)(W2 + (size_t)n2*UU*UU + (size_t)k*UU + v0 + c4*4);
    }
    #pragma unroll 8
    for (int i = 0; i < 64; ++i) sh[tx*STR + i] = g_hd[rr0+i][tx];
    __syncthreads();

    ull ac[4];
    #pragma unroll
    for (int j=0;j<4;++j) ac[j] = pack2(0.f,0.f);
    #pragma unroll 2
    for (int k = 0; k < 256; ++k){
        float w = sw2[k*32 + ul];
        ull w2 = pack2(w,w);
        const float* hrow = sh + k*STR + grp*8;
        ulonglong2 hA = *(const ulonglong2*)(hrow);
        ulonglong2 hB = *(const ulonglong2*)(hrow + 4);
        fma2(ac[0],hA.x,w2); fma2(ac[1],hA.y,w2);
        fma2(ac[2],hB.x,w2); fma2(ac[3],hB.y,w2);
    }
    #pragma unroll
    for (int j=0;j<4;++j){
        int rl = grp*8 + 2*j; float a0,a1; unpack2(ac[j],a0,a1);
        g_q[n2][rr0+rl][v0+ul]   = a0;
        g_q[n2][rr0+rl+1][v0+ul] = a1;
    }
}

__global__ __launch_bounds__(256) void k_dD(const float* __restrict__ av){
    __shared__ __align__(16) float q_s[256], v_s[256];
    __shared__ float sc_s[176];
    __shared__ __align__(16) float sred[1024];

    const int tx = threadIdx.x, lane = tx & 31, wid = tx >> 5;
    const int n3 = blockIdx.x >> 8, b = blockIdx.x & 255;

    q_s[tx] = g_q[n3][b][tx];
    v_s[tx] = av[n3*UU + tx];
    __syncthreads();

    const __nv_bfloat16* pj = &g_pjh[n3][0][0] + (size_t)b*TT*UU;
    #pragma unroll 3
    for (int ii = 0; ii < 21; ++ii){
        int t = wid*21 + ii;
        const uint2* row = (const uint2*)(pj + (size_t)t*UU);
        float acc = 0.f;
        #pragma unroll
        for (int j2 = 0; j2 < 2; ++j2){
            int v = j2*128 + 4*lane;
            uint2 pk = row[j2*32 + lane];
            float4 qv = *(const float4*)&q_s[v];
            float4 vv = *(const float4*)&v_s[v];
            acc += tanha(blo(pk.x) + qv.x) * vv.x;
            acc += tanha(bhi(pk.x) + qv.y) * vv.y;
            acc += tanha(blo(pk.y) + qv.z) * vv.z;
            acc += tanha(bhi(pk.y) + qv.w) * vv.w;
        }
        #pragma unroll
        for (int o = 16; o > 0; o >>= 1) acc += __shfl_xor_sync(0xffffffffu, acc, o);
        if (lane == 0) sc_s[t] = acc;
    }
    __syncthreads();
    if (wid == 0){
        float m = -1e30f;
        for (int t = lane; t < TT; t += 32) m = fmaxf(m, sc_s[t]);
        #pragma unroll
        for (int o = 16; o > 0; o >>= 1) m = fmaxf(m, __shfl_xor_sync(0xffffffffu, m, o));
        float ss = 0.f;
        for (int t = lane; t < TT; t += 32){ float e2 = __expf(sc_s[t]-m); sc_s[t] = e2; ss += e2; }
        #pragma unroll
        for (int o = 16; o > 0; o >>= 1) ss += __shfl_xor_sync(0xffffffffu, ss, o);
        float inv = __fdividef(1.f, ss);
        for (int t = lane; t < TT; t += 32) sc_s[t] *= inv;
    }
    __syncthreads();
    {
        int tg = tx >> 6, uq = tx & 63;
        const __nv_bfloat16* eob = &g_eoh[n3][0][0] + (size_t)b*TT*UU;
        float4 a = make_float4(0.f,0.f,0.f,0.f);
        #pragma unroll 6
        for (int i = 0; i < 42; ++i){
            int t = tg + 4*i;
            uint2 e = __ldcs((const uint2*)(eob + (size_t)t*UU) + uq);
            float w = sc_s[t];
            a.x += w*blo(e.x); a.y += w*bhi(e.x);
            a.z += w*blo(e.y); a.w += w*bhi(e.y);
        }
        ((float4*)sred)[tg*64 + uq] = a;
    }
    __syncthreads();
    {
        int uq = tx >> 2, comp = tx & 3;
        float sum = sred[(0*64 + uq)*4 + comp] + sred[(1*64 + uq)*4 + comp]
                  + sred[(2*64 + uq)*4 + comp] + sred[(3*64 + uq)*4 + comp];
        g_c[b][n3*UU + tx] = sum;
    }
}

// ---------------- head part 1 ----------------
__global__ __launch_bounds__(256) void k_h1(const float* __restrict__ W1, const float* __restrict__ b1){
    const int rem = blockIdx.x;
    const int r0 = (rem>>2)*32, j0 = (rem&3)*64;
    const int tx = threadIdx.x, ul = tx&63, grp = tx>>6;
    __shared__ __align__(16) float sh[256][34];
    ull acc[4];
    #pragma unroll
    for (int j=0;j<4;++j) acc[j]=pack2(0.f,0.f);
    for (int cc=0;cc<4;++cc){
        const float* src = (cc==0) ? &g_hd[0][0] : (&g_c[0][0] + (cc-1)*256);
        int stride = (cc==0) ? UU : U3;
        __syncthreads();
        #pragma unroll 8
        for (int i=0;i<32;++i) sh[tx][i] = src[(r0+i)*stride + tx];
        __syncthreads();
        const float* wp = W1 + cc*256*UU + j0 + ul;
        #pragma unroll 2
        for (int k=0;k<256;++k){
            float w = wp[k*UU];
            ull w2 = pack2(w,w);
            #pragma unroll
            for (int j=0;j<4;++j) fma2(acc[j], *(const ull*)&sh[k][(grp*4+j)*2], w2);
        }
    }
    float bb = b1[j0+ul];
    #pragma unroll
    for (int j=0;j<4;++j){
        int rl=(grp*4+j)*2; float a0,a1; unpack2(acc[j],a0,a1);
        g_s1[r0+rl][j0+ul]   = a0+bb;
        g_s1[r0+rl+1][j0+ul] = a1+bb;
    }
}

// ---------------- head part 2 ----------------
__global__ __launch_bounds__(256) void k_h2(const float* __restrict__ ef, const float* __restrict__ eW,
        const float* __restrict__ eb, const float* __restrict__ W1, const float* __restrict__ w2v,
        const float* __restrict__ b2, float* __restrict__ out){
    const int b = blockIdx.x, tx = threadIdx.x, lane = tx&31, wid = tx>>5;
    __shared__ __align__(16) float se[256][26];
    __shared__ float sf[384];
    __shared__ float prt[8][24];
    sf[tx < 384 ? tx : 0] = ef[b*384 + (tx < 384 ? tx : 0)];
    if (tx < 128) sf[256+tx] = ef[b*384 + 256 + tx];
    __syncthreads();
    float wk[16];
    #pragma unroll
    for (int k=0;k<16;++k) wk[k] = eW[k*UU + tx];
    float ebv = eb[tx];
    #pragma unroll
    for (int h=0;h<24;++h){
        float a = ebv;
        #pragma unroll
        for (int k=0;k<16;++k) a += sf[h*16+k]*wk[k];
        se[tx][h] = fmaxf(a, 0.f);
    }
    __syncthreads();
    ull y2[12];
    #pragma unroll
    for (int p=0;p<12;++p) y2[p]=pack2(0.f,0.f);
    const float* wp = W1 + 1024*UU + tx;
    #pragma unroll 2
    for (int k=0;k<256;++k){
        float w = wp[k*UU];
        ull w2 = pack2(w,w);
        #pragma unroll
        for (int p=0;p<12;++p) fma2(y2[p], *(const ull*)&se[k][2*p], w2);
    }
    float sp = g_s1[b][tx];
    float wo = w2v[tx];
    float ct[24];
    #pragma unroll
    for (int p=0;p<12;++p){
        float a0,a1; unpack2(y2[p],a0,a1);
        ct[2*p]   = fmaxf(sp+a0, 0.f)*wo;
        ct[2*p+1] = fmaxf(sp+a1, 0.f)*wo;
    }
    #pragma unroll
    for (int h=0;h<24;++h){
        #pragma unroll
        for (int o=16;o>0;o>>=1) ct[h] += __shfl_xor_sync(0xffffffffu, ct[h], o);
    }
    if (lane==0){
        #pragma unroll
        for (int h=0;h<24;++h) prt[wid][h] = ct[h];
    }
    __syncthreads();
    if (tx < 24){
        float s2 = b2[0];
        #pragma unroll
        for (int w=0;w<8;++w) s2 += prt[w][tx];
        out[b*HH + tx] = s2;
    }
}

extern "C" void kernel_launch(void* const* d_in, const int* in_sizes, int n_in,
                              void* d_out, int out_size){
    const float* enc_in = (const float*)d_in[0];
    const float* dec_in = (const float*)d_in[1];
    const float* ext_f  = (const float*)d_in[2];
    const float* enc_W  = (const float*)d_in[3];
    const float* enc_U  = (const float*)d_in[4];
    const float* enc_b  = (const float*)d_in[5];
    const float* att_W1 = (const float*)d_in[6];
    const float* att_W2 = (const float*)d_in[7];
    const float* att_v  = (const float*)d_in[8];
    const float* dec_W  = (const float*)d_in[9];
    const float* dec_U  = (const float*)d_in[10];
    const float* dec_b  = (const float*)d_in[11];
    const float* ext_W  = (const float*)d_in[12];
    const float* ext_b  = (const float*)d_in[13];
    const float* out1_W = (const float*)d_in[14];
    const float* out1_b = (const float*)d_in[15];
    const float* out2_W = (const float*)d_in[16];
    const float* out2_b = (const float*)d_in[17];
    float* out = (float*)d_out;

    const int enc_smem = E_TOT * 4;
    cudaFuncSetAttribute(k_enc, cudaFuncAttributeMaxDynamicSharedMemorySize, enc_smem);
    cudaFuncSetAttribute(k_dA, cudaFuncAttributeMaxDynamicSharedMemorySize, A_SMEM);
    cudaFuncSetAttribute(k_dC, cudaFuncAttributeMaxDynamicSharedMemorySize, C_SMEM);

    k_init<<<768,  256>>>();
    k_enc <<<96,   256, enc_smem>>>(enc_in, enc_W, enc_U, enc_b);
    k_proj<<<8064, 256>>>(att_W1);

    for (int s = 0; s < HH; ++s){
        k_dA<<<128, 256, A_SMEM>>>(dec_W, dec_U);
        k_dB<<<256, 256>>>(dec_W, dec_b, dec_in, s);
        k_dC<<<96,  256, C_SMEM>>>(att_W2);
        k_dD<<<768, 256>>>(att_v);
    }

    k_h1<<<32,  256>>>(out1_W, out1_b);
    k_h2<<<256, 256>>>(ext_f, ext_W, ext_b, out1_W, out2_W, out2_b, out);
}